// round 1
// baseline (speedup 1.0000x reference)
#include <cuda_runtime.h>
#include <cuda_fp16.h>
#include <cstdint>

// ---------------------------------------------------------------------------
// CompressedLinear: y = ((x @ Vh^T) * S) @ U^T + bias
//   x  [8192, 4096] fp32
//   Vh [1024, 4096] int (0..255), U [4096, 1024] int, S [1024] int
// Strategy: weights (int-128) are EXACT in fp16. Two fp16 tensor-core GEMMs
// with fp32 accumulate; scales folded between GEMMs in fp32.
// ---------------------------------------------------------------------------

#define M_TOK   8192
#define IN_F    4096
#define OUT_F   4096
#define RANK    1024

// Scratch (device globals: allocation-free rule)
__device__ __half g_x16[(size_t)M_TOK * IN_F];   // 64 MB
__device__ __half g_W1[(size_t)RANK * IN_F];     // 8 MB  (Vh - 128)
__device__ __half g_W2[(size_t)OUT_F * RANK];    // 8 MB  (U - 128)
__device__ __half g_H [(size_t)M_TOK * RANK];    // 16 MB (h * S, fp16)
__device__ float  g_hscale[RANK];

// ---------------------------- prep kernels ---------------------------------
__global__ void prep_x(const float* __restrict__ x) {
    size_t i = ((size_t)blockIdx.x * blockDim.x + threadIdx.x) * 4;
    float4 v = *(const float4*)(x + i);
    *(__half2*)(g_x16 + i)     = __floats2half2_rn(v.x, v.y);
    *(__half2*)(g_x16 + i + 2) = __floats2half2_rn(v.z, v.w);
}

__global__ void prep_w1(const int* __restrict__ v, const float* __restrict__ zp) {
    size_t i = ((size_t)blockIdx.x * blockDim.x + threadIdx.x) * 4;
    float z = *zp;
    int4 d = *(const int4*)(v + i);
    *(__half2*)(g_W1 + i)     = __floats2half2_rn((float)d.x - z, (float)d.y - z);
    *(__half2*)(g_W1 + i + 2) = __floats2half2_rn((float)d.z - z, (float)d.w - z);
}

__global__ void prep_w2(const int* __restrict__ v, const float* __restrict__ zp) {
    size_t i = ((size_t)blockIdx.x * blockDim.x + threadIdx.x) * 4;
    float z = *zp;
    int4 d = *(const int4*)(v + i);
    *(__half2*)(g_W2 + i)     = __floats2half2_rn((float)d.x - z, (float)d.y - z);
    *(__half2*)(g_W2 + i + 2) = __floats2half2_rn((float)d.z - z, (float)d.w - z);
}

__global__ void prep_hscale(const int* __restrict__ s_data,
                            const float* __restrict__ s_scale,
                            const float* __restrict__ s_zp,
                            const float* __restrict__ vh_scale) {
    int r = threadIdx.x + blockIdx.x * blockDim.x;
    if (r < RANK)
        g_hscale[r] = vh_scale[0] * s_scale[0] * ((float)s_data[r] - s_zp[0]);
}

// ----------------------------- GEMM core -----------------------------------
// C[M,N] = A[M,K] * B[N,K]^T, fp16 in, fp32 accum.
// CTA tile 128x128x32, 8 warps (2x4), warp tile 64x32, mma m16n8k16.
// 3-stage cp.async pipeline. Smem rows padded to 40 halfs (80B) -> conflict-free.

#define BK          32
#define SROW        40                  // halfs per smem row (32 data + 8 pad)
#define ATILE_H     (128 * SROW)        // 5120 halfs
#define STAGE_H     (2 * ATILE_H)       // A + B per stage
#define NSTAGES     3
#define SMEM_BYTES  (NSTAGES * STAGE_H * 2)

__device__ __forceinline__ void cp_async16(__half* sp, const __half* gp) {
    uint32_t s = (uint32_t)__cvta_generic_to_shared(sp);
    asm volatile("cp.async.cg.shared.global [%0], [%1], 16;\n" :: "r"(s), "l"(gp));
}
__device__ __forceinline__ void cp_commit() {
    asm volatile("cp.async.commit_group;\n");
}
template<int N> __device__ __forceinline__ void cp_wait() {
    asm volatile("cp.async.wait_group %0;\n" :: "n"(N));
}

__device__ __forceinline__ void mma16816(float* d, const uint32_t* a, const uint32_t* b) {
    asm volatile(
        "mma.sync.aligned.m16n8k16.row.col.f32.f16.f16.f32 "
        "{%0,%1,%2,%3}, {%4,%5,%6,%7}, {%8,%9}, {%0,%1,%2,%3};\n"
        : "+f"(d[0]), "+f"(d[1]), "+f"(d[2]), "+f"(d[3])
        : "r"(a[0]), "r"(a[1]), "r"(a[2]), "r"(a[3]), "r"(b[0]), "r"(b[1]));
}

__device__ __forceinline__ void load_tiles(const __half* __restrict__ A,
                                           const __half* __restrict__ B,
                                           __half* sm, int m0, int n0, int K, int kt) {
    int q = threadIdx.x;
#pragma unroll
    for (int rep = 0; rep < 2; rep++) {
        int qi = q + rep * 256;         // 0..511
        int row = qi >> 2, c = qi & 3;  // 128 rows x 4 chunks of 16B
        cp_async16(sm + row * SROW + c * 8,
                   A + (size_t)(m0 + row) * K + kt * BK + c * 8);
        cp_async16(sm + ATILE_H + row * SROW + c * 8,
                   B + (size_t)(n0 + row) * K + kt * BK + c * 8);
    }
}

// MODE 0: epilogue *= g_hscale[col], store __half to C
// MODE 1: epilogue = acc*uscale + bias[col], store float to C
template<int MODE>
__global__ void __launch_bounds__(256, 2)
gemm_kernel(const __half* __restrict__ A, const __half* __restrict__ B,
            void* __restrict__ Cv, int M, int N, int K,
            const float* __restrict__ vec,       // hscale (MODE0) or bias (MODE1)
            const float* __restrict__ uscale) {  // MODE1 only
    extern __shared__ __half sm[];

    const int m0 = blockIdx.y * 128;
    const int n0 = blockIdx.x * 128;
    const int KT = K / BK;

    const int warp = threadIdx.x >> 5;
    const int lane = threadIdx.x & 31;
    const int wm = (warp >> 2) * 64;    // warp row offset (0/64)
    const int wn = (warp & 3) * 32;     // warp col offset (0/32/64/96)
    const int g  = lane >> 2;           // group id 0..7
    const int tg = lane & 3;            // thread-in-group 0..3

    // prologue: preload NSTAGES-1 stages
#pragma unroll
    for (int s = 0; s < NSTAGES - 1; s++) {
        load_tiles(A, B, sm + s * STAGE_H, m0, n0, K, s);
        cp_commit();
    }
    cp_wait<NSTAGES - 2>();
    __syncthreads();

    float d[4][4][4];
#pragma unroll
    for (int i = 0; i < 4; i++)
#pragma unroll
        for (int j = 0; j < 4; j++)
#pragma unroll
            for (int c = 0; c < 4; c++) d[i][j][c] = 0.f;

    for (int kt = 0; kt < KT; kt++) {
        const __half* sA = sm + (kt % NSTAGES) * STAGE_H;
        const __half* sB = sA + ATILE_H;

#pragma unroll
        for (int ks = 0; ks < 2; ks++) {
            const int ko = ks * 16;
            uint32_t a[4][4], b[4][2];
#pragma unroll
            for (int i = 0; i < 4; i++) {
                const __half* p = sA + (wm + i * 16 + g) * SROW + ko + tg * 2;
                a[i][0] = *(const uint32_t*)p;
                a[i][1] = *(const uint32_t*)(p + 8 * SROW);
                a[i][2] = *(const uint32_t*)(p + 8);
                a[i][3] = *(const uint32_t*)(p + 8 * SROW + 8);
            }
#pragma unroll
            for (int j = 0; j < 4; j++) {
                const __half* p = sB + (wn + j * 8 + g) * SROW + ko + tg * 2;
                b[j][0] = *(const uint32_t*)p;
                b[j][1] = *(const uint32_t*)(p + 8);
            }
#pragma unroll
            for (int i = 0; i < 4; i++)
#pragma unroll
                for (int j = 0; j < 4; j++)
                    mma16816(d[i][j], a[i], b[j]);
        }

        // prefetch stage kt + NSTAGES - 1
        int nk = kt + NSTAGES - 1;
        if (nk < KT)
            load_tiles(A, B, sm + (nk % NSTAGES) * STAGE_H, m0, n0, K, nk);
        cp_commit();
        cp_wait<NSTAGES - 2>();
        __syncthreads();
    }

    // epilogue
    if (MODE == 0) {
        __half* C = (__half*)Cv;
#pragma unroll
        for (int i = 0; i < 4; i++) {
#pragma unroll
            for (int j = 0; j < 4; j++) {
                int col = n0 + wn + j * 8 + tg * 2;
                float s0 = vec[col], s1 = vec[col + 1];
                int r0 = m0 + wm + i * 16 + g;
                *(__half2*)(C + (size_t)r0 * N + col) =
                    __floats2half2_rn(d[i][j][0] * s0, d[i][j][1] * s1);
                *(__half2*)(C + (size_t)(r0 + 8) * N + col) =
                    __floats2half2_rn(d[i][j][2] * s0, d[i][j][3] * s1);
            }
        }
    } else {
        float* C = (float*)Cv;
        float us = __ldg(uscale);
#pragma unroll
        for (int i = 0; i < 4; i++) {
#pragma unroll
            for (int j = 0; j < 4; j++) {
                int col = n0 + wn + j * 8 + tg * 2;
                float b0 = vec[col], b1 = vec[col + 1];
                int r0 = m0 + wm + i * 16 + g;
                float2 v0 = make_float2(d[i][j][0] * us + b0, d[i][j][1] * us + b1);
                float2 v1 = make_float2(d[i][j][2] * us + b0, d[i][j][3] * us + b1);
                *(float2*)(C + (size_t)r0 * N + col) = v0;
                *(float2*)(C + (size_t)(r0 + 8) * N + col) = v1;
            }
        }
    }
}

// ------------------------------ launch -------------------------------------
extern "C" void kernel_launch(void* const* d_in, const int* in_sizes, int n_in,
                              void* d_out, int out_size) {
    const float* x        = (const float*)d_in[0];
    const int*   U_data   = (const int*)  d_in[1];
    const float* U_scale  = (const float*)d_in[2];
    // d_in[3] = U_zp (==128, same as others; we use Vh_zp/U_zp where needed)
    const float* U_zp     = (const float*)d_in[3];
    const int*   S_data   = (const int*)  d_in[4];
    const float* S_scale  = (const float*)d_in[5];
    const float* S_zp     = (const float*)d_in[6];
    const int*   Vh_data  = (const int*)  d_in[7];
    const float* Vh_scale = (const float*)d_in[8];
    const float* Vh_zp    = (const float*)d_in[9];
    const float* bias     = (const float*)d_in[10];
    float* out = (float*)d_out;

    (void)in_sizes; (void)n_in; (void)out_size;

    cudaFuncSetAttribute(gemm_kernel<0>,
                         cudaFuncAttributeMaxDynamicSharedMemorySize, SMEM_BYTES);
    cudaFuncSetAttribute(gemm_kernel<1>,
                         cudaFuncAttributeMaxDynamicSharedMemorySize, SMEM_BYTES);

    void *p_x16, *p_W1, *p_W2, *p_H, *p_hs;
    cudaGetSymbolAddress(&p_x16, g_x16);
    cudaGetSymbolAddress(&p_W1,  g_W1);
    cudaGetSymbolAddress(&p_W2,  g_W2);
    cudaGetSymbolAddress(&p_H,   g_H);
    cudaGetSymbolAddress(&p_hs,  g_hscale);

    // prep
    prep_x <<<(size_t)M_TOK * IN_F / 4 / 256, 256>>>(x);
    prep_w1<<<(size_t)RANK * IN_F / 4 / 256, 256>>>(Vh_data, Vh_zp);
    prep_w2<<<(size_t)OUT_F * RANK / 4 / 256, 256>>>(U_data, U_zp);
    prep_hscale<<<4, 256>>>(S_data, S_scale, S_zp, Vh_scale);

    // GEMM1: H[8192,1024] = x16 @ W1^T, scaled per-rank, fp16
    {
        dim3 grid(RANK / 128, M_TOK / 128);
        gemm_kernel<0><<<grid, 256, SMEM_BYTES>>>(
            (const __half*)p_x16, (const __half*)p_W1, p_H,
            M_TOK, RANK, IN_F, (const float*)p_hs, nullptr);
    }
    // GEMM2: out[8192,4096] = H @ W2^T * U_scale + bias, fp32
    {
        dim3 grid(OUT_F / 128, M_TOK / 128);
        gemm_kernel<1><<<grid, 256, SMEM_BYTES>>>(
            (const __half*)p_H, (const __half*)p_W2, out,
            M_TOK, OUT_F, RANK, bias, U_scale);
    }
}

// round 3
// speedup vs baseline: 1.0154x; 1.0154x over previous
#include <cuda_runtime.h>
#include <cuda_fp16.h>
#include <cstdint>

// ---------------------------------------------------------------------------
// CompressedLinear: y = ((x @ Vh^T) * S) @ U^T + bias
// Legacy mma.sync fp16 path (tcgen05 PTX rejected by this toolchain's
// compute_103 virtual arch). CTA tile 128x256x64, warp tile 64x64, 8 warps,
// 3-stage cp.async pipeline, padded smem rows (conflict-free).
// ---------------------------------------------------------------------------

#define M_TOK   8192
#define IN_F    4096
#define OUT_F   4096
#define RANK    1024

__device__ __half g_x16[(size_t)M_TOK * IN_F];   // 64 MB
__device__ __half g_W1[(size_t)RANK * IN_F];     // 8 MB  (Vh - 128)
__device__ __half g_W2[(size_t)OUT_F * RANK];    // 8 MB  (U - 128)
__device__ __half g_H [(size_t)M_TOK * RANK];    // 16 MB (h * hscale)
__device__ float  g_hscale[RANK];

// ---------------------------- prep kernels ---------------------------------
__global__ void prep_x(const float* __restrict__ x) {
    size_t i = ((size_t)blockIdx.x * blockDim.x + threadIdx.x) * 4;
    float4 v = *(const float4*)(x + i);
    *(__half2*)(g_x16 + i)     = __floats2half2_rn(v.x, v.y);
    *(__half2*)(g_x16 + i + 2) = __floats2half2_rn(v.z, v.w);
}
__global__ void prep_w1(const int* __restrict__ v, const float* __restrict__ zp) {
    size_t i = ((size_t)blockIdx.x * blockDim.x + threadIdx.x) * 4;
    float z = *zp;
    int4 d = *(const int4*)(v + i);
    *(__half2*)(g_W1 + i)     = __floats2half2_rn((float)d.x - z, (float)d.y - z);
    *(__half2*)(g_W1 + i + 2) = __floats2half2_rn((float)d.z - z, (float)d.w - z);
}
__global__ void prep_w2(const int* __restrict__ v, const float* __restrict__ zp) {
    size_t i = ((size_t)blockIdx.x * blockDim.x + threadIdx.x) * 4;
    float z = *zp;
    int4 d = *(const int4*)(v + i);
    *(__half2*)(g_W2 + i)     = __floats2half2_rn((float)d.x - z, (float)d.y - z);
    *(__half2*)(g_W2 + i + 2) = __floats2half2_rn((float)d.z - z, (float)d.w - z);
}
__global__ void prep_hscale(const int* __restrict__ s_data,
                            const float* __restrict__ s_scale,
                            const float* __restrict__ s_zp,
                            const float* __restrict__ vh_scale) {
    int r = threadIdx.x + blockIdx.x * blockDim.x;
    if (r < RANK)
        g_hscale[r] = vh_scale[0] * s_scale[0] * ((float)s_data[r] - s_zp[0]);
}

// ---------------------------- PTX helpers ----------------------------------
__device__ __forceinline__ void cp_async16(uint32_t saddr, const void* gp) {
    asm volatile("cp.async.cg.shared.global [%0], [%1], 16;\n" :: "r"(saddr), "l"(gp));
}
__device__ __forceinline__ void cp_commit() { asm volatile("cp.async.commit_group;\n"); }
template<int N> __device__ __forceinline__ void cp_wait() {
    asm volatile("cp.async.wait_group %0;\n" :: "n"(N));
}
__device__ __forceinline__ void mma16816(float* d, const uint32_t* a, const uint32_t* b) {
    asm volatile(
        "mma.sync.aligned.m16n8k16.row.col.f32.f16.f16.f32 "
        "{%0,%1,%2,%3}, {%4,%5,%6,%7}, {%8,%9}, {%0,%1,%2,%3};\n"
        : "+f"(d[0]), "+f"(d[1]), "+f"(d[2]), "+f"(d[3])
        : "r"(a[0]), "r"(a[1]), "r"(a[2]), "r"(a[3]), "r"(b[0]), "r"(b[1]));
}

// ----------------------------- GEMM kernel ---------------------------------
// C[M,N] = A[M,K] * B[N,K]^T, fp16 in, fp32 accum.
// CTA 128x256x64, 8 warps (2x4), warp tile 64x64. 3-stage cp.async pipeline.
// Smem rows padded: 64 data + 8 pad halfs (144B stride) -> conflict-free LDS.

#define TM      128
#define TN      256
#define BKH     64                  // halfs per K-slab
#define NSTG    3
#define SROW    72                  // halfs per smem row
#define A_H     (TM * SROW)         // 9216 halfs
#define B_H     (TN * SROW)         // 18432 halfs
#define STG_H   (A_H + B_H)         // 27648 halfs = 55296 B
#define SMEM_REQ (NSTG * STG_H * 2) // 165888 B

// MODE 0: C half, *= vec[col]; MODE 1: C float, = acc*(*uscale) + vec[col]
template<int MODE>
__global__ void __launch_bounds__(256, 1)
gemm_mma(const __half* __restrict__ A, const __half* __restrict__ B,
         void* __restrict__ Cv, int M, int N, int K,
         const float* __restrict__ vec, const float* __restrict__ uscale) {
    extern __shared__ __half sm[];
    const uint32_t smem_base = (uint32_t)__cvta_generic_to_shared(sm);

    const int tid  = threadIdx.x;
    const int warp = tid >> 5;
    const int lane = tid & 31;
    const int wm = (warp >> 2) * 64;    // warp row offset: 0 / 64
    const int wn = (warp & 3) * 64;     // warp col offset: 0/64/128/192
    const int g  = lane >> 2;           // 0..7
    const int tg = lane & 3;            // 0..3

    const int m0 = blockIdx.y * TM;
    const int n0 = blockIdx.x * TN;
    const int KT = K / BKH;

    // stage loader: per thread 4 A-chunks + 8 B-chunks of 16B
    auto load_stage = [&](int kt, int s) {
        const uint32_t tA = smem_base + (uint32_t)(s * STG_H) * 2;
        const uint32_t tB = tA + A_H * 2;
        const __half* gA = A + (size_t)m0 * K + (size_t)kt * BKH;
        const __half* gB = B + (size_t)n0 * K + (size_t)kt * BKH;
#pragma unroll
        for (int r = 0; r < 4; r++) {               // A: 1024 chunks (128 rows x 8)
            int i = tid + r * 256;
            int row = i >> 3, c = i & 7;
            cp_async16(tA + (uint32_t)(row * SROW + c * 8) * 2,
                       gA + (size_t)row * K + c * 8);
        }
#pragma unroll
        for (int r = 0; r < 8; r++) {               // B: 2048 chunks (256 rows x 8)
            int i = tid + r * 256;
            int row = i >> 3, c = i & 7;
            cp_async16(tB + (uint32_t)(row * SROW + c * 8) * 2,
                       gB + (size_t)row * K + c * 8);
        }
    };

    // prologue
#pragma unroll
    for (int s = 0; s < NSTG - 1; s++) { load_stage(s, s); cp_commit(); }

    float d[4][8][4];
#pragma unroll
    for (int i = 0; i < 4; i++)
#pragma unroll
        for (int j = 0; j < 8; j++)
#pragma unroll
            for (int c = 0; c < 4; c++) d[i][j][c] = 0.f;

    for (int kt = 0; kt < KT; kt++) {
        cp_wait<NSTG - 2>();
        __syncthreads();

        // issue next stage's loads BEFORE compute (overlap DMA with MMA)
        const int nk = kt + NSTG - 1;
        if (nk < KT) load_stage(nk, nk % NSTG);
        cp_commit();

        const __half* sA = sm + (kt % NSTG) * STG_H;
        const __half* sB = sA + A_H;

#pragma unroll
        for (int ks = 0; ks < 4; ks++) {
            const int ko = ks * 16;
            uint32_t a[4][4], b[8][2];
#pragma unroll
            for (int i = 0; i < 4; i++) {
                const __half* p = sA + (wm + i * 16 + g) * SROW + ko + tg * 2;
                a[i][0] = *(const uint32_t*)p;
                a[i][1] = *(const uint32_t*)(p + 8 * SROW);
                a[i][2] = *(const uint32_t*)(p + 8);
                a[i][3] = *(const uint32_t*)(p + 8 * SROW + 8);
            }
#pragma unroll
            for (int j = 0; j < 8; j++) {
                const __half* p = sB + (wn + j * 8 + g) * SROW + ko + tg * 2;
                b[j][0] = *(const uint32_t*)p;
                b[j][1] = *(const uint32_t*)(p + 8);
            }
#pragma unroll
            for (int i = 0; i < 4; i++)
#pragma unroll
                for (int j = 0; j < 8; j++)
                    mma16816(d[i][j], a[i], b[j]);
        }
    }

    // epilogue
    if (MODE == 0) {
        __half* C = (__half*)Cv;
#pragma unroll
        for (int i = 0; i < 4; i++) {
#pragma unroll
            for (int j = 0; j < 8; j++) {
                int col = n0 + wn + j * 8 + tg * 2;
                float s0 = vec[col], s1 = vec[col + 1];
                int r0 = m0 + wm + i * 16 + g;
                *(__half2*)(C + (size_t)r0 * N + col) =
                    __floats2half2_rn(d[i][j][0] * s0, d[i][j][1] * s1);
                *(__half2*)(C + (size_t)(r0 + 8) * N + col) =
                    __floats2half2_rn(d[i][j][2] * s0, d[i][j][3] * s1);
            }
        }
    } else {
        float* C = (float*)Cv;
        const float us = __ldg(uscale);
#pragma unroll
        for (int i = 0; i < 4; i++) {
#pragma unroll
            for (int j = 0; j < 8; j++) {
                int col = n0 + wn + j * 8 + tg * 2;
                float b0 = vec[col], b1 = vec[col + 1];
                int r0 = m0 + wm + i * 16 + g;
                *(float2*)(C + (size_t)r0 * N + col) =
                    make_float2(d[i][j][0] * us + b0, d[i][j][1] * us + b1);
                *(float2*)(C + (size_t)(r0 + 8) * N + col) =
                    make_float2(d[i][j][2] * us + b0, d[i][j][3] * us + b1);
            }
        }
    }
}

// ------------------------------ launch -------------------------------------
extern "C" void kernel_launch(void* const* d_in, const int* in_sizes, int n_in,
                              void* d_out, int out_size) {
    const float* x        = (const float*)d_in[0];
    const int*   U_data   = (const int*)  d_in[1];
    const float* U_scale  = (const float*)d_in[2];
    const float* U_zp     = (const float*)d_in[3];
    const int*   S_data   = (const int*)  d_in[4];
    const float* S_scale  = (const float*)d_in[5];
    const float* S_zp     = (const float*)d_in[6];
    const int*   Vh_data  = (const int*)  d_in[7];
    const float* Vh_scale = (const float*)d_in[8];
    const float* Vh_zp    = (const float*)d_in[9];
    const float* bias     = (const float*)d_in[10];
    float* out = (float*)d_out;
    (void)in_sizes; (void)n_in; (void)out_size;

    cudaFuncSetAttribute(gemm_mma<0>, cudaFuncAttributeMaxDynamicSharedMemorySize, SMEM_REQ);
    cudaFuncSetAttribute(gemm_mma<1>, cudaFuncAttributeMaxDynamicSharedMemorySize, SMEM_REQ);

    void *p_x16, *p_W1, *p_W2, *p_H, *p_hs;
    cudaGetSymbolAddress(&p_x16, g_x16);
    cudaGetSymbolAddress(&p_W1,  g_W1);
    cudaGetSymbolAddress(&p_W2,  g_W2);
    cudaGetSymbolAddress(&p_H,   g_H);
    cudaGetSymbolAddress(&p_hs,  g_hscale);

    prep_x <<<(size_t)M_TOK * IN_F / 4 / 256, 256>>>(x);
    prep_w1<<<(size_t)RANK * IN_F / 4 / 256, 256>>>(Vh_data, Vh_zp);
    prep_w2<<<(size_t)OUT_F * RANK / 4 / 256, 256>>>(U_data, U_zp);
    prep_hscale<<<4, 256>>>(S_data, S_scale, S_zp, Vh_scale);

    // GEMM1: H[8192,1024] = x16 @ W1^T (*hscale per col), fp16 out
    {
        dim3 grid(RANK / TN, M_TOK / TM);
        gemm_mma<0><<<grid, 256, SMEM_REQ>>>(
            (const __half*)p_x16, (const __half*)p_W1, p_H,
            M_TOK, RANK, IN_F, (const float*)p_hs, nullptr);
    }
    // GEMM2: out[8192,4096] = H @ W2^T * U_scale + bias, fp32
    {
        dim3 grid(OUT_F / TN, M_TOK / TM);
        gemm_mma<1><<<grid, 256, SMEM_REQ>>>(
            (const __half*)p_H, (const __half*)p_W2, out,
            M_TOK, OUT_F, RANK, bias, U_scale);
    }
}

// round 5
// speedup vs baseline: 1.0538x; 1.0378x over previous
#include <cuda_runtime.h>
#include <cuda_fp16.h>
#include <cstdint>

// ---------------------------------------------------------------------------
// CompressedLinear: y = ((x @ Vh^T) * S) @ U^T + bias
// Legacy mma.sync fp16 path (tcgen05 rejected by compute_103 toolchain).
// Measured ceiling: ~512 MAC/cyc/SM on the HMMA pipe -> GEMMs ~477us floor.
// This round: fold x fp32->fp16 conversion into GEMM1 (A staged as fp32,
// packed with cvt.rn.f16x2.f32 at frag load), merge all prep into one kernel.
// ---------------------------------------------------------------------------

#define M_TOK   8192
#define IN_F    4096
#define OUT_F   4096
#define RANK    1024

__device__ __half g_W1[(size_t)RANK * IN_F];     // 8 MB  (Vh - 128)
__device__ __half g_W2[(size_t)OUT_F * RANK];    // 8 MB  (U - 128)
__device__ __half g_H [(size_t)M_TOK * RANK];    // 16 MB (h * hscale)
__device__ float  g_hscale[RANK];

// ------------------------- merged prep kernel ------------------------------
#define NW1_CH  ((size_t)RANK * IN_F / 4)        // 1,048,576 int4 chunks
#define NW2_CH  ((size_t)OUT_F * RANK / 4)       // 1,048,576

__global__ void prep_all(const int* __restrict__ Vh_data, const float* __restrict__ Vh_zp,
                         const int* __restrict__ U_data,  const float* __restrict__ U_zp,
                         const int* __restrict__ S_data,  const float* __restrict__ S_scale,
                         const float* __restrict__ S_zp,  const float* __restrict__ Vh_scale) {
    size_t g = (size_t)blockIdx.x * blockDim.x + threadIdx.x;
    if (g < NW1_CH) {
        size_t i = g * 4;
        float z = *Vh_zp;
        int4 d = *(const int4*)(Vh_data + i);
        *(__half2*)(g_W1 + i)     = __floats2half2_rn((float)d.x - z, (float)d.y - z);
        *(__half2*)(g_W1 + i + 2) = __floats2half2_rn((float)d.z - z, (float)d.w - z);
    } else if (g < NW1_CH + NW2_CH) {
        size_t i = (g - NW1_CH) * 4;
        float z = *U_zp;
        int4 d = *(const int4*)(U_data + i);
        *(__half2*)(g_W2 + i)     = __floats2half2_rn((float)d.x - z, (float)d.y - z);
        *(__half2*)(g_W2 + i + 2) = __floats2half2_rn((float)d.z - z, (float)d.w - z);
    } else if (g < NW1_CH + NW2_CH + RANK) {
        int r = (int)(g - NW1_CH - NW2_CH);
        g_hscale[r] = Vh_scale[0] * S_scale[0] * ((float)S_data[r] - S_zp[0]);
    }
}

// ---------------------------- PTX helpers ----------------------------------
__device__ __forceinline__ void cp_async16(uint32_t saddr, const void* gp) {
    asm volatile("cp.async.cg.shared.global [%0], [%1], 16;\n" :: "r"(saddr), "l"(gp));
}
__device__ __forceinline__ void cp_commit() { asm volatile("cp.async.commit_group;\n"); }
template<int N> __device__ __forceinline__ void cp_wait() {
    asm volatile("cp.async.wait_group %0;\n" :: "n"(N));
}
__device__ __forceinline__ void mma16816(float* d, const uint32_t* a, const uint32_t* b) {
    asm volatile(
        "mma.sync.aligned.m16n8k16.row.col.f32.f16.f16.f32 "
        "{%0,%1,%2,%3}, {%4,%5,%6,%7}, {%8,%9}, {%0,%1,%2,%3};\n"
        : "+f"(d[0]), "+f"(d[1]), "+f"(d[2]), "+f"(d[3])
        : "r"(a[0]), "r"(a[1]), "r"(a[2]), "r"(a[3]), "r"(b[0]), "r"(b[1]));
}
// pack two fp32 -> one b32 holding f16x2 (lo = x, hi = y)
__device__ __forceinline__ uint32_t pack_f16x2(float x, float y) {
    uint32_t r;
    asm("cvt.rn.f16x2.f32 %0, %1, %2;" : "=r"(r) : "f"(y), "f"(x));
    return r;
}

// ----------------------------- GEMM kernel ---------------------------------
// C[M,N] = A[M,K] * B[N,K]^T. CTA 128x256x64, 8 warps (2x4), warp tile 64x64,
// 3-stage cp.async pipeline, padded smem rows.
// AFP32=1: A staged as fp32 in smem (raw x), packed to fp16 at frag load.
// MODE 0: C half, *= vec[col]; MODE 1: C float, = acc*(*uscale) + vec[col].

#define TM      128
#define TN      256
#define BKH     64
#define NSTG    3
#define SROW    72                          // elems per smem row (64 + 8 pad)
#define B_BYTES (TN * SROW * 2)             // 36864
#define A_BYTES_16 (TM * SROW * 2)          // 18432
#define A_BYTES_32 (TM * SROW * 4)          // 36864
#define STG_B(AFP32)   ((AFP32 ? A_BYTES_32 : A_BYTES_16) + B_BYTES)
#define SMEM_REQ(AFP32) (NSTG * STG_B(AFP32))

template<int MODE, int AFP32>
__global__ void __launch_bounds__(256, 1)
gemm_mma(const void* __restrict__ Av, const __half* __restrict__ B,
         void* __restrict__ Cv, int M, int N, int K,
         const float* __restrict__ vec, const float* __restrict__ uscale) {
    extern __shared__ char smc[];
    const uint32_t smem_base = (uint32_t)__cvta_generic_to_shared(smc);
    constexpr int A_BYTES = AFP32 ? A_BYTES_32 : A_BYTES_16;
    constexpr int STG_BYTES = A_BYTES + B_BYTES;

    const int tid  = threadIdx.x;
    const int warp = tid >> 5;
    const int lane = tid & 31;
    const int wm = (warp >> 2) * 64;
    const int wn = (warp & 3) * 64;
    const int g  = lane >> 2;
    const int tg = lane & 3;

    const int m0 = blockIdx.y * TM;
    const int n0 = blockIdx.x * TN;
    const int KT = K / BKH;

    auto load_stage = [&](int kt, int s) {
        const uint32_t tA = smem_base + (uint32_t)(s * STG_BYTES);
        const uint32_t tB = tA + A_BYTES;
        if (AFP32) {
            const float* gA = (const float*)Av + (size_t)m0 * K + (size_t)kt * BKH;
#pragma unroll
            for (int r = 0; r < 8; r++) {           // 2048 chunks: 128 rows x 16
                int i = tid + r * 256;
                int row = i >> 4, c = i & 15;
                cp_async16(tA + (uint32_t)(row * SROW + c * 4) * 4,
                           gA + (size_t)row * K + c * 4);
            }
        } else {
            const __half* gA = (const __half*)Av + (size_t)m0 * K + (size_t)kt * BKH;
#pragma unroll
            for (int r = 0; r < 4; r++) {           // 1024 chunks: 128 rows x 8
                int i = tid + r * 256;
                int row = i >> 3, c = i & 7;
                cp_async16(tA + (uint32_t)(row * SROW + c * 8) * 2,
                           gA + (size_t)row * K + c * 8);
            }
        }
        const __half* gB = B + (size_t)n0 * K + (size_t)kt * BKH;
#pragma unroll
        for (int r = 0; r < 8; r++) {               // 2048 chunks: 256 rows x 8
            int i = tid + r * 256;
            int row = i >> 3, c = i & 7;
            cp_async16(tB + (uint32_t)(row * SROW + c * 8) * 2,
                       gB + (size_t)row * K + c * 8);
        }
    };

#pragma unroll
    for (int s = 0; s < NSTG - 1; s++) { load_stage(s, s); cp_commit(); }

    float d[4][8][4];
#pragma unroll
    for (int i = 0; i < 4; i++)
#pragma unroll
        for (int j = 0; j < 8; j++)
#pragma unroll
            for (int c = 0; c < 4; c++) d[i][j][c] = 0.f;

    for (int kt = 0; kt < KT; kt++) {
        cp_wait<NSTG - 2>();
        __syncthreads();

        const int nk = kt + NSTG - 1;
        if (nk < KT) load_stage(nk, nk % NSTG);
        cp_commit();

        const char* stg = smc + (kt % NSTG) * STG_BYTES;
        const __half* sB = (const __half*)(stg + A_BYTES);

#pragma unroll
        for (int ks = 0; ks < 4; ks++) {
            const int ko = ks * 16;
            uint32_t a[4][4], b[8][2];
            if (AFP32) {
                const float* sA = (const float*)stg;
#pragma unroll
                for (int i = 0; i < 4; i++) {
                    const float* p = sA + (wm + i * 16 + g) * SROW + ko + tg * 2;
                    float2 v0 = *(const float2*)p;
                    float2 v1 = *(const float2*)(p + 8 * SROW);
                    float2 v2 = *(const float2*)(p + 8);
                    float2 v3 = *(const float2*)(p + 8 * SROW + 8);
                    a[i][0] = pack_f16x2(v0.x, v0.y);
                    a[i][1] = pack_f16x2(v1.x, v1.y);
                    a[i][2] = pack_f16x2(v2.x, v2.y);
                    a[i][3] = pack_f16x2(v3.x, v3.y);
                }
            } else {
                const __half* sA = (const __half*)stg;
#pragma unroll
                for (int i = 0; i < 4; i++) {
                    const __half* p = sA + (wm + i * 16 + g) * SROW + ko + tg * 2;
                    a[i][0] = *(const uint32_t*)p;
                    a[i][1] = *(const uint32_t*)(p + 8 * SROW);
                    a[i][2] = *(const uint32_t*)(p + 8);
                    a[i][3] = *(const uint32_t*)(p + 8 * SROW + 8);
                }
            }
#pragma unroll
            for (int j = 0; j < 8; j++) {
                const __half* p = sB + (wn + j * 8 + g) * SROW + ko + tg * 2;
                b[j][0] = *(const uint32_t*)p;
                b[j][1] = *(const uint32_t*)(p + 8);
            }
#pragma unroll
            for (int i = 0; i < 4; i++)
#pragma unroll
                for (int j = 0; j < 8; j++)
                    mma16816(d[i][j], a[i], b[j]);
        }
    }

    // epilogue
    if (MODE == 0) {
        __half* C = (__half*)Cv;
#pragma unroll
        for (int i = 0; i < 4; i++) {
#pragma unroll
            for (int j = 0; j < 8; j++) {
                int col = n0 + wn + j * 8 + tg * 2;
                float s0 = vec[col], s1 = vec[col + 1];
                int r0 = m0 + wm + i * 16 + g;
                *(__half2*)(C + (size_t)r0 * N + col) =
                    __floats2half2_rn(d[i][j][0] * s0, d[i][j][1] * s1);
                *(__half2*)(C + (size_t)(r0 + 8) * N + col) =
                    __floats2half2_rn(d[i][j][2] * s0, d[i][j][3] * s1);
            }
        }
    } else {
        float* C = (float*)Cv;
        const float us = __ldg(uscale);
#pragma unroll
        for (int i = 0; i < 4; i++) {
#pragma unroll
            for (int j = 0; j < 8; j++) {
                int col = n0 + wn + j * 8 + tg * 2;
                float b0 = vec[col], b1 = vec[col + 1];
                int r0 = m0 + wm + i * 16 + g;
                *(float2*)(C + (size_t)r0 * N + col) =
                    make_float2(d[i][j][0] * us + b0, d[i][j][1] * us + b1);
                *(float2*)(C + (size_t)(r0 + 8) * N + col) =
                    make_float2(d[i][j][2] * us + b0, d[i][j][3] * us + b1);
            }
        }
    }
}

// ------------------------------ launch -------------------------------------
extern "C" void kernel_launch(void* const* d_in, const int* in_sizes, int n_in,
                              void* d_out, int out_size) {
    const float* x        = (const float*)d_in[0];
    const int*   U_data   = (const int*)  d_in[1];
    const float* U_scale  = (const float*)d_in[2];
    const float* U_zp     = (const float*)d_in[3];
    const int*   S_data   = (const int*)  d_in[4];
    const float* S_scale  = (const float*)d_in[5];
    const float* S_zp     = (const float*)d_in[6];
    const int*   Vh_data  = (const int*)  d_in[7];
    const float* Vh_scale = (const float*)d_in[8];
    const float* Vh_zp    = (const float*)d_in[9];
    const float* bias     = (const float*)d_in[10];
    float* out = (float*)d_out;
    (void)in_sizes; (void)n_in; (void)out_size;

    cudaFuncSetAttribute((const void*)gemm_mma<0, 1>,
                         cudaFuncAttributeMaxDynamicSharedMemorySize, SMEM_REQ(1));
    cudaFuncSetAttribute((const void*)gemm_mma<1, 0>,
                         cudaFuncAttributeMaxDynamicSharedMemorySize, SMEM_REQ(0));

    void *p_W1, *p_W2, *p_H, *p_hs;
    cudaGetSymbolAddress(&p_W1, g_W1);
    cudaGetSymbolAddress(&p_W2, g_W2);
    cudaGetSymbolAddress(&p_H,  g_H);
    cudaGetSymbolAddress(&p_hs, g_hscale);

    // one prep launch: W1, W2, hscale
    {
        size_t total = NW1_CH + NW2_CH + RANK;
        prep_all<<<(unsigned)((total + 255) / 256), 256>>>(
            Vh_data, Vh_zp, U_data, U_zp, S_data, S_scale, S_zp, Vh_scale);
    }

    // GEMM1: H[8192,1024] = fp16(x) @ W1^T (*hscale per col); A read as fp32
    {
        dim3 grid(RANK / TN, M_TOK / TM);
        gemm_mma<0, 1><<<grid, 256, SMEM_REQ(1)>>>(
            x, (const __half*)p_W1, p_H,
            M_TOK, RANK, IN_F, (const float*)p_hs, nullptr);
    }
    // GEMM2: out[8192,4096] = H @ W2^T * U_scale + bias
    {
        dim3 grid(OUT_F / TN, M_TOK / TM);
        gemm_mma<1, 0><<<grid, 256, SMEM_REQ(0)>>>(
            p_H, (const __half*)p_W2, out,
            M_TOK, OUT_F, RANK, bias, U_scale);
    }
}

// round 6
// speedup vs baseline: 1.1261x; 1.0686x over previous
#include <cuda_runtime.h>
#include <cuda_fp16.h>
#include <cstdint>

// ---------------------------------------------------------------------------
// CompressedLinear: y = ((x @ Vh^T) * S) @ U^T + bias
// mma.sync fp16 path at the HMMA pipe ceiling (~512 MAC/cyc/SM).
// This round: single fused launch for BOTH GEMMs with per-M-block flag
// dependencies, so GEMM2 tiles backfill SMs idled by GEMM1's partial wave.
// ---------------------------------------------------------------------------

#define M_TOK   8192
#define IN_F    4096
#define OUT_F   4096
#define RANK    1024

#define TM      128
#define TN      256
#define G1_TN_TILES (RANK / TN)      // 4
#define G1_TILES    ((M_TOK / TM) * G1_TN_TILES)   // 256
#define G2_TN_TILES (OUT_F / TN)     // 16
#define G2_TILES    ((M_TOK / TM) * G2_TN_TILES)   // 1024
#define MBLKS       (M_TOK / TM)     // 64

__device__ __half g_W1[(size_t)RANK * IN_F];     // 8 MB  (Vh - 128)
__device__ __half g_W2[(size_t)OUT_F * RANK];    // 8 MB  (U - 128)
__device__ __half g_H [(size_t)M_TOK * RANK];    // 16 MB (h * hscale)
__device__ float  g_hscale[RANK];
__device__ int    g_flags[MBLKS];

// ------------------------- merged prep kernel ------------------------------
#define NW1_CH  ((size_t)RANK * IN_F / 4)
#define NW2_CH  ((size_t)OUT_F * RANK / 4)

__global__ void prep_all(const int* __restrict__ Vh_data, const float* __restrict__ Vh_zp,
                         const int* __restrict__ U_data,  const float* __restrict__ U_zp,
                         const int* __restrict__ S_data,  const float* __restrict__ S_scale,
                         const float* __restrict__ S_zp,  const float* __restrict__ Vh_scale) {
    size_t g = (size_t)blockIdx.x * blockDim.x + threadIdx.x;
    if (g < NW1_CH) {
        size_t i = g * 4;
        float z = *Vh_zp;
        int4 d = *(const int4*)(Vh_data + i);
        *(__half2*)(g_W1 + i)     = __floats2half2_rn((float)d.x - z, (float)d.y - z);
        *(__half2*)(g_W1 + i + 2) = __floats2half2_rn((float)d.z - z, (float)d.w - z);
    } else if (g < NW1_CH + NW2_CH) {
        size_t i = (g - NW1_CH) * 4;
        float z = *U_zp;
        int4 d = *(const int4*)(U_data + i);
        *(__half2*)(g_W2 + i)     = __floats2half2_rn((float)d.x - z, (float)d.y - z);
        *(__half2*)(g_W2 + i + 2) = __floats2half2_rn((float)d.z - z, (float)d.w - z);
    } else if (g < NW1_CH + NW2_CH + RANK) {
        int r = (int)(g - NW1_CH - NW2_CH);
        g_hscale[r] = Vh_scale[0] * S_scale[0] * ((float)S_data[r] - S_zp[0]);
    } else if (g < NW1_CH + NW2_CH + RANK + MBLKS) {
        g_flags[g - NW1_CH - NW2_CH - RANK] = 0;
    }
}

// ---------------------------- PTX helpers ----------------------------------
__device__ __forceinline__ void cp_async16(uint32_t saddr, const void* gp) {
    asm volatile("cp.async.cg.shared.global [%0], [%1], 16;\n" :: "r"(saddr), "l"(gp));
}
__device__ __forceinline__ void cp_commit() { asm volatile("cp.async.commit_group;\n"); }
template<int N> __device__ __forceinline__ void cp_wait() {
    asm volatile("cp.async.wait_group %0;\n" :: "n"(N));
}
__device__ __forceinline__ void mma16816(float* d, const uint32_t* a, const uint32_t* b) {
    asm volatile(
        "mma.sync.aligned.m16n8k16.row.col.f32.f16.f16.f32 "
        "{%0,%1,%2,%3}, {%4,%5,%6,%7}, {%8,%9}, {%0,%1,%2,%3};\n"
        : "+f"(d[0]), "+f"(d[1]), "+f"(d[2]), "+f"(d[3])
        : "r"(a[0]), "r"(a[1]), "r"(a[2]), "r"(a[3]), "r"(b[0]), "r"(b[1]));
}
__device__ __forceinline__ uint32_t pack_f16x2(float x, float y) {
    uint32_t r;
    asm("cvt.rn.f16x2.f32 %0, %1, %2;" : "=r"(r) : "f"(y), "f"(x));
    return r;
}
__device__ __forceinline__ int ld_acquire_gpu(const int* p) {
    int v;
    asm volatile("ld.acquire.gpu.s32 %0, [%1];" : "=r"(v) : "l"(p) : "memory");
    return v;
}

// ----------------------------- GEMM body -----------------------------------
#define BKH     64
#define NSTG    3
#define SROW    72
#define B_BYTES (TN * SROW * 2)             // 36864
#define A_BYTES_16 (TM * SROW * 2)          // 18432
#define A_BYTES_32 (TM * SROW * 4)          // 36864
#define SMEM_MAX (NSTG * (A_BYTES_32 + B_BYTES))   // 221184

template<int MODE, int AFP32>
__device__ __forceinline__ void
gemm_body(const void* __restrict__ Av, const __half* __restrict__ B,
          void* __restrict__ Cv, int N, int K,
          const float* __restrict__ vec, float us,
          int m0, int n0, char* smc) {
    const uint32_t smem_base = (uint32_t)__cvta_generic_to_shared(smc);
    constexpr int A_BYTES = AFP32 ? A_BYTES_32 : A_BYTES_16;
    constexpr int STG_BYTES = A_BYTES + B_BYTES;

    const int tid  = threadIdx.x;
    const int warp = tid >> 5;
    const int lane = tid & 31;
    const int wm = (warp >> 2) * 64;
    const int wn = (warp & 3) * 64;
    const int g  = lane >> 2;
    const int tg = lane & 3;
    const int KT = K / BKH;

    auto load_stage = [&](int kt, int s) {
        const uint32_t tA = smem_base + (uint32_t)(s * STG_BYTES);
        const uint32_t tB = tA + A_BYTES;
        if (AFP32) {
            const float* gA = (const float*)Av + (size_t)m0 * K + (size_t)kt * BKH;
#pragma unroll
            for (int r = 0; r < 8; r++) {
                int i = tid + r * 256;
                int row = i >> 4, c = i & 15;
                cp_async16(tA + (uint32_t)(row * SROW + c * 4) * 4,
                           gA + (size_t)row * K + c * 4);
            }
        } else {
            const __half* gA = (const __half*)Av + (size_t)m0 * K + (size_t)kt * BKH;
#pragma unroll
            for (int r = 0; r < 4; r++) {
                int i = tid + r * 256;
                int row = i >> 3, c = i & 7;
                cp_async16(tA + (uint32_t)(row * SROW + c * 8) * 2,
                           gA + (size_t)row * K + c * 8);
            }
        }
        const __half* gB = B + (size_t)n0 * K + (size_t)kt * BKH;
#pragma unroll
        for (int r = 0; r < 8; r++) {
            int i = tid + r * 256;
            int row = i >> 3, c = i & 7;
            cp_async16(tB + (uint32_t)(row * SROW + c * 8) * 2,
                       gB + (size_t)row * K + c * 8);
        }
    };

#pragma unroll
    for (int s = 0; s < NSTG - 1; s++) { load_stage(s, s); cp_commit(); }

    float d[4][8][4];
#pragma unroll
    for (int i = 0; i < 4; i++)
#pragma unroll
        for (int j = 0; j < 8; j++)
#pragma unroll
            for (int c = 0; c < 4; c++) d[i][j][c] = 0.f;

    for (int kt = 0; kt < KT; kt++) {
        cp_wait<NSTG - 2>();
        __syncthreads();

        const int nk = kt + NSTG - 1;
        if (nk < KT) load_stage(nk, nk % NSTG);
        cp_commit();

        const char* stg = smc + (kt % NSTG) * STG_BYTES;
        const __half* sB = (const __half*)(stg + A_BYTES);

#pragma unroll
        for (int ks = 0; ks < 4; ks++) {
            const int ko = ks * 16;
            uint32_t a[4][4], b[8][2];
            if (AFP32) {
                const float* sA = (const float*)stg;
#pragma unroll
                for (int i = 0; i < 4; i++) {
                    const float* p = sA + (wm + i * 16 + g) * SROW + ko + tg * 2;
                    float2 v0 = *(const float2*)p;
                    float2 v1 = *(const float2*)(p + 8 * SROW);
                    float2 v2 = *(const float2*)(p + 8);
                    float2 v3 = *(const float2*)(p + 8 * SROW + 8);
                    a[i][0] = pack_f16x2(v0.x, v0.y);
                    a[i][1] = pack_f16x2(v1.x, v1.y);
                    a[i][2] = pack_f16x2(v2.x, v2.y);
                    a[i][3] = pack_f16x2(v3.x, v3.y);
                }
            } else {
                const __half* sA = (const __half*)stg;
#pragma unroll
                for (int i = 0; i < 4; i++) {
                    const __half* p = sA + (wm + i * 16 + g) * SROW + ko + tg * 2;
                    a[i][0] = *(const uint32_t*)p;
                    a[i][1] = *(const uint32_t*)(p + 8 * SROW);
                    a[i][2] = *(const uint32_t*)(p + 8);
                    a[i][3] = *(const uint32_t*)(p + 8 * SROW + 8);
                }
            }
#pragma unroll
            for (int j = 0; j < 8; j++) {
                const __half* p = sB + (wn + j * 8 + g) * SROW + ko + tg * 2;
                b[j][0] = *(const uint32_t*)p;
                b[j][1] = *(const uint32_t*)(p + 8);
            }
#pragma unroll
            for (int i = 0; i < 4; i++)
#pragma unroll
                for (int j = 0; j < 8; j++)
                    mma16816(d[i][j], a[i], b[j]);
        }
    }

    if (MODE == 0) {
        __half* C = (__half*)Cv;
#pragma unroll
        for (int i = 0; i < 4; i++) {
#pragma unroll
            for (int j = 0; j < 8; j++) {
                int col = n0 + wn + j * 8 + tg * 2;
                float s0 = vec[col], s1 = vec[col + 1];
                int r0 = m0 + wm + i * 16 + g;
                *(__half2*)(C + (size_t)r0 * N + col) =
                    __floats2half2_rn(d[i][j][0] * s0, d[i][j][1] * s1);
                *(__half2*)(C + (size_t)(r0 + 8) * N + col) =
                    __floats2half2_rn(d[i][j][2] * s0, d[i][j][3] * s1);
            }
        }
    } else {
        float* C = (float*)Cv;
#pragma unroll
        for (int i = 0; i < 4; i++) {
#pragma unroll
            for (int j = 0; j < 8; j++) {
                int col = n0 + wn + j * 8 + tg * 2;
                float b0 = vec[col], b1 = vec[col + 1];
                int r0 = m0 + wm + i * 16 + g;
                *(float2*)(C + (size_t)r0 * N + col) =
                    make_float2(d[i][j][0] * us + b0, d[i][j][1] * us + b1);
                *(float2*)(C + (size_t)(r0 + 8) * N + col) =
                    make_float2(d[i][j][2] * us + b0, d[i][j][3] * us + b1);
            }
        }
    }
}

// --------------------------- fused GEMM kernel ------------------------------
// bids [0, 256): GEMM1 tiles (m-major). bids [256, 1280): GEMM2 tiles (m-major).
__global__ void __launch_bounds__(256, 1)
fused_gemm(const float* __restrict__ x, float* __restrict__ out,
           const float* __restrict__ uscale, const float* __restrict__ bias) {
    extern __shared__ char smc[];
    const int bid = blockIdx.x;

    if (bid < G1_TILES) {
        const int mb = bid >> 2;             // m-major: 4 n-tiles per m-block
        const int n0 = (bid & 3) * TN;
        gemm_body<0, 1>(x, g_W1, g_H, RANK, IN_F, g_hscale, 0.f,
                        mb * TM, n0, smc);
        // publish: H rows [mb*TM, +128) cols [n0, +256) complete
        __threadfence();
        __syncthreads();
        if (threadIdx.x == 0) atomicAdd(&g_flags[mb], 1);
    } else {
        const int b2 = bid - G1_TILES;
        const int mb = b2 >> 4;              // m-major: 16 n-tiles per m-block
        const int n0 = (b2 & 15) * TN;
        if (threadIdx.x == 0) {
            while (ld_acquire_gpu(&g_flags[mb]) < G1_TN_TILES) { }
        }
        __syncthreads();
        const float us = __ldg(uscale);
        gemm_body<1, 0>(g_H, g_W2, out, OUT_F, RANK, bias, us,
                        mb * TM, n0, smc);
    }
}

// ------------------------------ launch -------------------------------------
extern "C" void kernel_launch(void* const* d_in, const int* in_sizes, int n_in,
                              void* d_out, int out_size) {
    const float* x        = (const float*)d_in[0];
    const int*   U_data   = (const int*)  d_in[1];
    const float* U_scale  = (const float*)d_in[2];
    const float* U_zp     = (const float*)d_in[3];
    const int*   S_data   = (const int*)  d_in[4];
    const float* S_scale  = (const float*)d_in[5];
    const float* S_zp     = (const float*)d_in[6];
    const int*   Vh_data  = (const int*)  d_in[7];
    const float* Vh_scale = (const float*)d_in[8];
    const float* Vh_zp    = (const float*)d_in[9];
    const float* bias     = (const float*)d_in[10];
    float* out = (float*)d_out;
    (void)in_sizes; (void)n_in; (void)out_size;

    cudaFuncSetAttribute(fused_gemm, cudaFuncAttributeMaxDynamicSharedMemorySize,
                         SMEM_MAX);

    // prep: W1, W2, hscale, flag reset
    {
        size_t total = NW1_CH + NW2_CH + RANK + MBLKS;
        prep_all<<<(unsigned)((total + 255) / 256), 256>>>(
            Vh_data, Vh_zp, U_data, U_zp, S_data, S_scale, S_zp, Vh_scale);
    }
    // fused GEMM1 + GEMM2 (flag-based cross-tile dependency)
    fused_gemm<<<G1_TILES + G2_TILES, 256, SMEM_MAX>>>(x, out, U_scale, bias);
}

// round 8
// speedup vs baseline: 1.2324x; 1.0943x over previous
#include <cuda_runtime.h>
#include <cuda_fp16.h>
#include <cstdint>

// ---------------------------------------------------------------------------
// CompressedLinear: y = ((x @ Vh^T) * S) @ U^T + bias
// mma.sync fp16 path. R6 ncu: tensor=51%, occ=12.4% (1 CTA/SM, 221KB smem)
// -> pipe idles at pipeline sync points. This round: 128x128 tiles, 128 thr
// (4 warps @ 64x64), smem 110.6KB -> 2 CTAs/SM so barriers overlap compute.
// GEMM1: A fp32-staged NSTG=2; GEMM2: fp16 NSTG=3. Fused launch + flags.
// (R7 fix: load_stage trip counts for the 128-row tile: A32=16, A16=8, B=8.)
// ---------------------------------------------------------------------------

#define M_TOK   8192
#define IN_F    4096
#define OUT_F   4096
#define RANK    1024

#define TM      128
#define TN      128
#define G1_TN_TILES (RANK / TN)                    // 8
#define G1_TILES    ((M_TOK / TM) * G1_TN_TILES)   // 512
#define G2_TN_TILES (OUT_F / TN)                   // 32
#define G2_TILES    ((M_TOK / TM) * G2_TN_TILES)   // 2048
#define MBLKS       (M_TOK / TM)                   // 64

__device__ __half g_W1[(size_t)RANK * IN_F];     // 8 MB  (Vh - 128)
__device__ __half g_W2[(size_t)OUT_F * RANK];    // 8 MB  (U - 128)
__device__ __half g_H [(size_t)M_TOK * RANK];    // 16 MB (h * hscale)
__device__ float  g_hscale[RANK];
__device__ int    g_flags[MBLKS];

// ------------------------- merged prep kernel ------------------------------
#define NW1_CH  ((size_t)RANK * IN_F / 4)
#define NW2_CH  ((size_t)OUT_F * RANK / 4)

__global__ void prep_all(const int* __restrict__ Vh_data, const float* __restrict__ Vh_zp,
                         const int* __restrict__ U_data,  const float* __restrict__ U_zp,
                         const int* __restrict__ S_data,  const float* __restrict__ S_scale,
                         const float* __restrict__ S_zp,  const float* __restrict__ Vh_scale) {
    size_t g = (size_t)blockIdx.x * blockDim.x + threadIdx.x;
    if (g < NW1_CH) {
        size_t i = g * 4;
        float z = *Vh_zp;
        int4 d = *(const int4*)(Vh_data + i);
        *(__half2*)(g_W1 + i)     = __floats2half2_rn((float)d.x - z, (float)d.y - z);
        *(__half2*)(g_W1 + i + 2) = __floats2half2_rn((float)d.z - z, (float)d.w - z);
    } else if (g < NW1_CH + NW2_CH) {
        size_t i = (g - NW1_CH) * 4;
        float z = *U_zp;
        int4 d = *(const int4*)(U_data + i);
        *(__half2*)(g_W2 + i)     = __floats2half2_rn((float)d.x - z, (float)d.y - z);
        *(__half2*)(g_W2 + i + 2) = __floats2half2_rn((float)d.z - z, (float)d.w - z);
    } else if (g < NW1_CH + NW2_CH + RANK) {
        int r = (int)(g - NW1_CH - NW2_CH);
        g_hscale[r] = Vh_scale[0] * S_scale[0] * ((float)S_data[r] - S_zp[0]);
    } else if (g < NW1_CH + NW2_CH + RANK + MBLKS) {
        g_flags[g - NW1_CH - NW2_CH - RANK] = 0;
    }
}

// ---------------------------- PTX helpers ----------------------------------
__device__ __forceinline__ void cp_async16(uint32_t saddr, const void* gp) {
    asm volatile("cp.async.cg.shared.global [%0], [%1], 16;\n" :: "r"(saddr), "l"(gp));
}
__device__ __forceinline__ void cp_commit() { asm volatile("cp.async.commit_group;\n"); }
template<int N> __device__ __forceinline__ void cp_wait() {
    asm volatile("cp.async.wait_group %0;\n" :: "n"(N));
}
__device__ __forceinline__ void mma16816(float* d, const uint32_t* a, const uint32_t* b) {
    asm volatile(
        "mma.sync.aligned.m16n8k16.row.col.f32.f16.f16.f32 "
        "{%0,%1,%2,%3}, {%4,%5,%6,%7}, {%8,%9}, {%0,%1,%2,%3};\n"
        : "+f"(d[0]), "+f"(d[1]), "+f"(d[2]), "+f"(d[3])
        : "r"(a[0]), "r"(a[1]), "r"(a[2]), "r"(a[3]), "r"(b[0]), "r"(b[1]));
}
__device__ __forceinline__ uint32_t pack_f16x2(float x, float y) {
    uint32_t r;
    asm("cvt.rn.f16x2.f32 %0, %1, %2;" : "=r"(r) : "f"(y), "f"(x));
    return r;
}
__device__ __forceinline__ int ld_acquire_gpu(const int* p) {
    int v;
    asm volatile("ld.acquire.gpu.s32 %0, [%1];" : "=r"(v) : "l"(p) : "memory");
    return v;
}

// ----------------------------- GEMM body -----------------------------------
#define BKH     64
#define SROW    72
#define B_BYTES (TN * SROW * 2)             // 18432
#define A_BYTES_16 (TM * SROW * 2)          // 18432
#define A_BYTES_32 (TM * SROW * 4)          // 36864
#define SMEM_USE 110592                     // both paths: exactly this

// MODE 0 (GEMM1): AFP32=1, NSTG=2.  MODE 1 (GEMM2): AFP32=0, NSTG=3.
template<int MODE, int AFP32, int NSTG>
__device__ __forceinline__ void
gemm_body(const void* __restrict__ Av, const __half* __restrict__ B,
          void* __restrict__ Cv, int N, int K,
          const float* __restrict__ vec, float us,
          int m0, int n0, char* smc) {
    const uint32_t smem_base = (uint32_t)__cvta_generic_to_shared(smc);
    constexpr int A_BYTES = AFP32 ? A_BYTES_32 : A_BYTES_16;
    constexpr int STG_BYTES = A_BYTES + B_BYTES;

    const int tid  = threadIdx.x;
    const int warp = tid >> 5;
    const int lane = tid & 31;
    const int wm = (warp >> 1) * 64;        // 0 / 64
    const int wn = (warp & 1) * 64;         // 0 / 64
    const int g  = lane >> 2;
    const int tg = lane & 3;
    const int KT = K / BKH;

    auto load_stage = [&](int kt, int s) {
        const uint32_t tA = smem_base + (uint32_t)(s * STG_BYTES);
        const uint32_t tB = tA + A_BYTES;
        if (AFP32) {
            const float* gA = (const float*)Av + (size_t)m0 * K + (size_t)kt * BKH;
#pragma unroll
            for (int r = 0; r < 16; r++) {          // 2048 chunks: 128 rows x 16
                int i = tid + r * 128;
                int row = i >> 4, c = i & 15;
                cp_async16(tA + (uint32_t)(row * SROW + c * 4) * 4,
                           gA + (size_t)row * K + c * 4);
            }
        } else {
            const __half* gA = (const __half*)Av + (size_t)m0 * K + (size_t)kt * BKH;
#pragma unroll
            for (int r = 0; r < 8; r++) {           // 1024 chunks: 128 rows x 8
                int i = tid + r * 128;
                int row = i >> 3, c = i & 7;
                cp_async16(tA + (uint32_t)(row * SROW + c * 8) * 2,
                           gA + (size_t)row * K + c * 8);
            }
        }
        const __half* gB = B + (size_t)n0 * K + (size_t)kt * BKH;
#pragma unroll
        for (int r = 0; r < 8; r++) {               // 1024 chunks: 128 rows x 8
            int i = tid + r * 128;
            int row = i >> 3, c = i & 7;
            cp_async16(tB + (uint32_t)(row * SROW + c * 8) * 2,
                       gB + (size_t)row * K + c * 8);
        }
    };

#pragma unroll
    for (int s = 0; s < NSTG - 1; s++) { load_stage(s, s); cp_commit(); }

    float d[4][8][4];
#pragma unroll
    for (int i = 0; i < 4; i++)
#pragma unroll
        for (int j = 0; j < 8; j++)
#pragma unroll
            for (int c = 0; c < 4; c++) d[i][j][c] = 0.f;

    for (int kt = 0; kt < KT; kt++) {
        cp_wait<NSTG - 2>();
        __syncthreads();

        const int nk = kt + NSTG - 1;
        if (nk < KT) load_stage(nk, nk % NSTG);
        cp_commit();

        const char* stg = smc + (kt % NSTG) * STG_BYTES;
        const __half* sB = (const __half*)(stg + A_BYTES);

#pragma unroll
        for (int ks = 0; ks < 4; ks++) {
            const int ko = ks * 16;
            uint32_t a[4][4], b[8][2];
            if (AFP32) {
                const float* sA = (const float*)stg;
#pragma unroll
                for (int i = 0; i < 4; i++) {
                    const float* p = sA + (wm + i * 16 + g) * SROW + ko + tg * 2;
                    float2 v0 = *(const float2*)p;
                    float2 v1 = *(const float2*)(p + 8 * SROW);
                    float2 v2 = *(const float2*)(p + 8);
                    float2 v3 = *(const float2*)(p + 8 * SROW + 8);
                    a[i][0] = pack_f16x2(v0.x, v0.y);
                    a[i][1] = pack_f16x2(v1.x, v1.y);
                    a[i][2] = pack_f16x2(v2.x, v2.y);
                    a[i][3] = pack_f16x2(v3.x, v3.y);
                }
            } else {
                const __half* sA = (const __half*)stg;
#pragma unroll
                for (int i = 0; i < 4; i++) {
                    const __half* p = sA + (wm + i * 16 + g) * SROW + ko + tg * 2;
                    a[i][0] = *(const uint32_t*)p;
                    a[i][1] = *(const uint32_t*)(p + 8 * SROW);
                    a[i][2] = *(const uint32_t*)(p + 8);
                    a[i][3] = *(const uint32_t*)(p + 8 * SROW + 8);
                }
            }
#pragma unroll
            for (int j = 0; j < 8; j++) {
                const __half* p = sB + (wn + j * 8 + g) * SROW + ko + tg * 2;
                b[j][0] = *(const uint32_t*)p;
                b[j][1] = *(const uint32_t*)(p + 8);
            }
#pragma unroll
            for (int i = 0; i < 4; i++)
#pragma unroll
                for (int j = 0; j < 8; j++)
                    mma16816(d[i][j], a[i], b[j]);
        }
    }

    if (MODE == 0) {
        __half* C = (__half*)Cv;
#pragma unroll
        for (int i = 0; i < 4; i++) {
#pragma unroll
            for (int j = 0; j < 8; j++) {
                int col = n0 + wn + j * 8 + tg * 2;
                float s0 = vec[col], s1 = vec[col + 1];
                int r0 = m0 + wm + i * 16 + g;
                *(__half2*)(C + (size_t)r0 * N + col) =
                    __floats2half2_rn(d[i][j][0] * s0, d[i][j][1] * s1);
                *(__half2*)(C + (size_t)(r0 + 8) * N + col) =
                    __floats2half2_rn(d[i][j][2] * s0, d[i][j][3] * s1);
            }
        }
    } else {
        float* C = (float*)Cv;
#pragma unroll
        for (int i = 0; i < 4; i++) {
#pragma unroll
            for (int j = 0; j < 8; j++) {
                int col = n0 + wn + j * 8 + tg * 2;
                float b0 = vec[col], b1 = vec[col + 1];
                int r0 = m0 + wm + i * 16 + g;
                *(float2*)(C + (size_t)r0 * N + col) =
                    make_float2(d[i][j][0] * us + b0, d[i][j][1] * us + b1);
                *(float2*)(C + (size_t)(r0 + 8) * N + col) =
                    make_float2(d[i][j][2] * us + b0, d[i][j][3] * us + b1);
            }
        }
    }
}

// --------------------------- fused GEMM kernel ------------------------------
// bids [0, 512): GEMM1 tiles (m-major). bids [512, 2560): GEMM2 tiles (m-major).
__global__ void __launch_bounds__(128, 2)
fused_gemm(const float* __restrict__ x, float* __restrict__ out,
           const float* __restrict__ uscale, const float* __restrict__ bias) {
    extern __shared__ char smc[];
    const int bid = blockIdx.x;

    if (bid < G1_TILES) {
        const int mb = bid >> 3;             // 8 n-tiles per m-block
        const int n0 = (bid & 7) * TN;
        gemm_body<0, 1, 2>(x, g_W1, g_H, RANK, IN_F, g_hscale, 0.f,
                           mb * TM, n0, smc);
        __threadfence();
        __syncthreads();
        if (threadIdx.x == 0) atomicAdd(&g_flags[mb], 1);
    } else {
        const int b2 = bid - G1_TILES;
        const int mb = b2 >> 5;              // 32 n-tiles per m-block
        const int n0 = (b2 & 31) * TN;
        if (threadIdx.x == 0) {
            while (ld_acquire_gpu(&g_flags[mb]) < G1_TN_TILES) { }
        }
        __syncthreads();
        const float us = __ldg(uscale);
        gemm_body<1, 0, 3>(g_H, g_W2, out, OUT_F, RANK, bias, us,
                           mb * TM, n0, smc);
    }
}

// ------------------------------ launch -------------------------------------
extern "C" void kernel_launch(void* const* d_in, const int* in_sizes, int n_in,
                              void* d_out, int out_size) {
    const float* x        = (const float*)d_in[0];
    const int*   U_data   = (const int*)  d_in[1];
    const float* U_scale  = (const float*)d_in[2];
    const float* U_zp     = (const float*)d_in[3];
    const int*   S_data   = (const int*)  d_in[4];
    const float* S_scale  = (const float*)d_in[5];
    const float* S_zp     = (const float*)d_in[6];
    const int*   Vh_data  = (const int*)  d_in[7];
    const float* Vh_scale = (const float*)d_in[8];
    const float* Vh_zp    = (const float*)d_in[9];
    const float* bias     = (const float*)d_in[10];
    float* out = (float*)d_out;
    (void)in_sizes; (void)n_in; (void)out_size;

    cudaFuncSetAttribute(fused_gemm, cudaFuncAttributeMaxDynamicSharedMemorySize,
                         SMEM_USE);

    // prep: W1, W2, hscale, flag reset
    {
        size_t total = NW1_CH + NW2_CH + RANK + MBLKS;
        prep_all<<<(unsigned)((total + 255) / 256), 256>>>(
            Vh_data, Vh_zp, U_data, U_zp, S_data, S_scale, S_zp, Vh_scale);
    }
    // fused GEMM1 + GEMM2 (flag-based cross-tile dependency)
    fused_gemm<<<G1_TILES + G2_TILES, 128, SMEM_USE>>>(x, out, U_scale, bias);
}